// round 16
// baseline (speedup 1.0000x reference)
#include <cuda_runtime.h>
#include <math.h>

#define VOLD   256
#define NGAUSS 4000
// Tile shape 8 x 8 x 16 (x,y,z); warp per tile (work-stealing), 4 warps/block.
#define TSX 8
#define TSY 8
#define TSZ 16
#define NTX 32
#define NTY 32
#define NTZ 16
#define NTILES (NTX * NTY * NTZ)      // 16384
#define CAP    32
#define SLICE  32                     // wx[8] wy[8] wz[16]

// ---------------------------------------------------------------------------
// Static device scratch. Zeroed at module load. prep resets g_next; gather
// self-cleans g_cnt — invariants hold across correctness run, capture, replays.
// ---------------------------------------------------------------------------
__device__ int g_cnt[NTILES];
__device__ int g_ids[NTILES * CAP];   // 2 MB
__device__ int g_next;                // work-stealing cursor for gather

// ---------------------------------------------------------------------------
// Kernel 1: binning only. Warp per Gaussian (8 per 256-thread block).
// Lanes 0-2 compute the per-axis tile bbox; broadcast; lane-per-pair
// atomic + id store (~28 pairs -> one iteration).
// ---------------------------------------------------------------------------
__global__ __launch_bounds__(256) void prep_kernel(
    const float* __restrict__ centers,
    const float* __restrict__ sigmas)
{
    const int warp = threadIdx.x >> 5;
    const int lane = threadIdx.x & 31;
    const int g    = blockIdx.x * 8 + warp;

    if (blockIdx.x == 0 && threadIdx.x == 0) g_next = 0;  // reset work cursor

    int tmin = 0, tcnt = 0;
    if (lane < 3) {
        const float sig = sigmas[g];
        const float cn  = centers[3 * g + lane];
        const float cv  = cn * 255.0f;
        const float cut = 3.0f * sig * 255.0f;

        const float minf = fmaxf(cv - cut, 0.0f);
        const float maxf = fminf(cv + cut, 255.0f);
        const int   mini = (int)floorf(minf);
        const int   maxi = min((int)floorf(maxf) + 1, VOLD);   // exclusive

        const int shf = (lane == 2) ? 4 : 3;
        tmin = mini >> shf;
        tcnt = ((maxi - 1) >> shf) - tmin + 1;
    }
    const int x0 = __shfl_sync(0xffffffffu, tmin, 0);
    const int y0 = __shfl_sync(0xffffffffu, tmin, 1);
    const int z0 = __shfl_sync(0xffffffffu, tmin, 2);
    const int nx = __shfl_sync(0xffffffffu, tcnt, 0);
    const int ny = __shfl_sync(0xffffffffu, tcnt, 1);
    const int nz = __shfl_sync(0xffffffffu, tcnt, 2);

    const int total = nx * ny * nz;          // <= ~48
    for (int i = lane; i < total; i += 32) {
        const int iz = i % nz;
        const int r  = i / nz;
        const int iy = r % ny;
        const int ix = r / ny;
        const int tile = ((x0 + ix) * NTY + (y0 + iy)) * NTZ + (z0 + iz);

        const int slot = atomicAdd(&g_cnt[tile], 1);
        if (slot < CAP) g_ids[tile * CAP + slot] = g;
    }
}

// ---------------------------------------------------------------------------
// Kernel 2: gather, persistent warps work-stealing 8x8x16 tiles.
// Phase 1: lane p derives pair p's params + packed per-axis bounds -> shared.
// Phase 2: weight loop (LDS params, precomputed bounds, no bbox math).
// Phase 3: FMA with lane = (y, zq); acc over all 8 x; per-x STG.128 where
// each 4-lane group writes a contiguous 64B z-row.
// ---------------------------------------------------------------------------
__global__ __launch_bounds__(128, 8) void gather_kernel(
    const float* __restrict__ centers,
    const float* __restrict__ sigmas,
    const float* __restrict__ intens,
    float* __restrict__ vol)
{
    const int warp = threadIdx.x >> 5;
    const int lane = threadIdx.x & 31;

    __shared__ __align__(16) float s_w[4][CAP * SLICE];    // 16 KB
    __shared__ float s_par[4][CAP][5];                     // c0 c1 c2 a I
    __shared__ int   s_bnd[4][CAP][3];                     // (maxi<<16)|mini

    // Lane roles (tile-independent parts)
    const int axis = min(lane >> 3, 2);
    const int o    = lane - (axis << 3);
    const int y    = lane >> 2;             // 0..7  (FMA phase)
    const int zq   = lane & 3;              // 0..3
    const float* __restrict__ swp = s_w[warp];

    for (;;) {
        int tile;
        if (lane == 0) tile = atomicAdd(&g_next, 1);
        tile = __shfl_sync(0xffffffffu, tile, 0);
        if (tile >= NTILES) break;

        const int cnt = min(g_cnt[tile], CAP);
        if (lane == 0) g_cnt[tile] = 0;   // restore invariant for next launch

        // Phase 1: per-lane param + bounds derivation (parallel, full MLP)
        if (lane < cnt) {
            const int gid = g_ids[tile * CAP + lane];
            const float sig = sigmas[gid];
            const float c0 = centers[3 * gid + 0];
            const float c1 = centers[3 * gid + 1];
            const float c2 = centers[3 * gid + 2];
            s_par[warp][lane][0] = c0;
            s_par[warp][lane][1] = c1;
            s_par[warp][lane][2] = c2;
            s_par[warp][lane][3] = __fdividef(0.5f, sig * sig);
            s_par[warp][lane][4] = intens[gid];
            const float cut = 3.0f * sig * 255.0f;
#pragma unroll
            for (int ax = 0; ax < 3; ++ax) {
                const float cv = ((ax == 0) ? c0 : (ax == 1) ? c1 : c2) * 255.0f;
                const float minf = fmaxf(cv - cut, 0.0f);
                const float maxf = fminf(cv + cut, 255.0f);
                const int   mini = (int)floorf(minf);
                const int   maxi = min((int)floorf(maxf) + 1, VOLD);
                s_bnd[warp][lane][ax] = (maxi << 16) | mini;
            }
        }
        __syncwarp();

        const int tzi = tile & (NTZ - 1);
        const int tyi = (tile >> 4) & (NTY - 1);
        const int txi = tile >> 9;

        // Phase 2: weight loop. Lanes 0-7 wx, 8-15 wy, 16-31 wz.
        {
            const int tb = (axis == 0) ? txi * TSX
                         : ((axis == 1) ? tyi * TSY : tzi * TSZ);
            const int idxv = tb + o;
            const float pos = (float)idxv * (1.0f / 255.0f);

#pragma unroll 4
            for (int p = 0; p < cnt; ++p) {
                const float c   = s_par[warp][p][axis];
                const float a   = s_par[warp][p][3];
                const int   bnd = s_bnd[warp][p][axis];
                const int   mini = bnd & 0xFFFF;
                const int   maxi = bnd >> 16;

                float w = 0.0f;
                if (idxv >= mini && idxv < maxi) {
                    const float d = pos - c;
                    w = __expf(-d * d * a);
                }
                if (axis == 0) w *= s_par[warp][p][4];
                s_w[warp][p * SLICE + lane] = w;
            }
        }
        __syncwarp();

        // Phase 3: FMA. Lane owns (y, zq); accumulate all 8 x slabs.
        float acc[8][4];
#pragma unroll
        for (int i = 0; i < 8; ++i)
#pragma unroll
            for (int j = 0; j < 4; ++j) acc[i][j] = 0.f;

#pragma unroll 2
        for (int p = 0; p < cnt; ++p) {
            const float* s = swp + p * SLICE;
            const float  wy = s[8 + y];                       // 8 distinct
            const float4 wz = *(const float4*)(s + 16 + 4 * zq);  // 64B/warp
            float4 tz;
            tz.x = wy * wz.x; tz.y = wy * wz.y;
            tz.z = wy * wz.z; tz.w = wy * wz.w;
            const float4 wxa = *(const float4*)(s);           // warp-uniform
            const float4 wxb = *(const float4*)(s + 4);       // warp-uniform
            const float wx[8] = { wxa.x, wxa.y, wxa.z, wxa.w,
                                  wxb.x, wxb.y, wxb.z, wxb.w };
#pragma unroll
            for (int xx = 0; xx < 8; ++xx) {
                acc[xx][0] = fmaf(wx[xx], tz.x, acc[xx][0]);
                acc[xx][1] = fmaf(wx[xx], tz.y, acc[xx][1]);
                acc[xx][2] = fmaf(wx[xx], tz.z, acc[xx][2]);
                acc[xx][3] = fmaf(wx[xx], tz.w, acc[xx][3]);
            }
        }
        __syncwarp();   // buffer reuse safe before next stolen tile

        // Stores: per x one STG.128; 4-lane groups write contiguous 64B rows.
        float* base = vol + ((size_t)(txi * TSX) * VOLD + (tyi * TSY + y)) * VOLD
                          + tzi * TSZ + 4 * zq;
#pragma unroll
        for (int xx = 0; xx < 8; ++xx) {
            *(float4*)(base + (size_t)xx * VOLD * VOLD) =
                make_float4(acc[xx][0], acc[xx][1], acc[xx][2], acc[xx][3]);
        }
    }
}

// ---------------------------------------------------------------------------
extern "C" void kernel_launch(void* const* d_in, const int* in_sizes, int n_in,
                              void* d_out, int out_size) {
    const float* centers = (const float*)d_in[0];
    const float* sigmas  = (const float*)d_in[1];
    const float* intens  = (const float*)d_in[2];
    float* vol = (float*)d_out;

    prep_kernel<<<NGAUSS / 8, 256>>>(centers, sigmas);
    gather_kernel<<<1184, 128>>>(centers, sigmas, intens, vol);
}

// round 17
// speedup vs baseline: 2.6291x; 2.6291x over previous
#include <cuda_runtime.h>
#include <math.h>

#define VOLD   256
#define NGAUSS 4000
// Tile shape 8 x 8 x 16 (x,y,z); warp per tile, 4 tiles per 128-thread block.
#define TSX 8
#define TSY 8
#define TSZ 16
#define NTX 32
#define NTY 32
#define NTZ 16
#define NTILES (NTX * NTY * NTZ)      // 16384
#define CAP    32
#define SLICE  32                     // wx[8] wy[8] wz[16]

// ---------------------------------------------------------------------------
// Static device scratch. Zeroed at module load; gather self-cleans g_cnt each
// launch, so the invariant holds across correctness run, capture, and replays.
// g_ids needs no cleaning: only entries [0, cnt) are ever read.
// ---------------------------------------------------------------------------
__device__ int g_cnt[NTILES];
__device__ int g_ids[NTILES * CAP];   // 2 MB

// ---------------------------------------------------------------------------
// Kernel 1: binning only. Warp per Gaussian (8 per 256-thread block).
// Lanes 0-2 compute the per-axis tile bbox; broadcast; lane-per-pair
// atomic + id store (~28 pairs -> one iteration).
// ---------------------------------------------------------------------------
__global__ __launch_bounds__(256) void prep_kernel(
    const float* __restrict__ centers,
    const float* __restrict__ sigmas)
{
    const int warp = threadIdx.x >> 5;
    const int lane = threadIdx.x & 31;
    const int g    = blockIdx.x * 8 + warp;

    int tmin = 0, tcnt = 0;
    if (lane < 3) {
        const float sig = sigmas[g];
        const float cn  = centers[3 * g + lane];
        const float cv  = cn * 255.0f;
        const float cut = 3.0f * sig * 255.0f;

        const float minf = fmaxf(cv - cut, 0.0f);
        const float maxf = fminf(cv + cut, 255.0f);
        const int   mini = (int)floorf(minf);
        const int   maxi = min((int)floorf(maxf) + 1, VOLD);   // exclusive

        const int shf = (lane == 2) ? 4 : 3;
        tmin = mini >> shf;
        tcnt = ((maxi - 1) >> shf) - tmin + 1;
    }
    const int x0 = __shfl_sync(0xffffffffu, tmin, 0);
    const int y0 = __shfl_sync(0xffffffffu, tmin, 1);
    const int z0 = __shfl_sync(0xffffffffu, tmin, 2);
    const int nx = __shfl_sync(0xffffffffu, tcnt, 0);
    const int ny = __shfl_sync(0xffffffffu, tcnt, 1);
    const int nz = __shfl_sync(0xffffffffu, tcnt, 2);

    const int total = nx * ny * nz;          // <= ~48
    for (int i = lane; i < total; i += 32) {
        const int iz = i % nz;
        const int r  = i / nz;
        const int iy = r % ny;
        const int ix = r / ny;
        const int tile = ((x0 + ix) * NTY + (y0 + iy)) * NTZ + (z0 + iz);

        const int slot = atomicAdd(&g_cnt[tile], 1);
        if (slot < CAP) g_ids[tile * CAP + slot] = g;
    }
}

// ---------------------------------------------------------------------------
// Kernel 2: gather, warp per 8x8x16 tile (4 per 128-thread block), static
// tile assignment. Phase 1: lane p derives pair p's params + packed bounds.
// Phase 2: weight loop (no bbox math). Phase 3: FMA with lane = (y, zq),
// acc over all 8 x; per-x STG.128 with 4-lane contiguous 64B z-rows.
// ---------------------------------------------------------------------------
__global__ __launch_bounds__(128, 8) void gather_kernel(
    const float* __restrict__ centers,
    const float* __restrict__ sigmas,
    const float* __restrict__ intens,
    float* __restrict__ vol)
{
    const int warp = threadIdx.x >> 5;
    const int lane = threadIdx.x & 31;
    const int tile = blockIdx.x * 4 + warp;

    __shared__ __align__(16) float s_w[4][CAP * SLICE];    // 16 KB
    __shared__ float s_par[4][CAP][5];                     // c0 c1 c2 a I
    __shared__ int   s_bnd[4][CAP][3];                     // (maxi<<16)|mini

    const int cnt = min(g_cnt[tile], CAP);

    // Phase 1: per-lane param + bounds derivation (parallel, full MLP)
    if (lane < cnt) {
        const int gid = g_ids[tile * CAP + lane];
        const float sig = sigmas[gid];
        const float c0 = centers[3 * gid + 0];
        const float c1 = centers[3 * gid + 1];
        const float c2 = centers[3 * gid + 2];
        s_par[warp][lane][0] = c0;
        s_par[warp][lane][1] = c1;
        s_par[warp][lane][2] = c2;
        s_par[warp][lane][3] = __fdividef(0.5f, sig * sig);
        s_par[warp][lane][4] = intens[gid];
        const float cut = 3.0f * sig * 255.0f;
#pragma unroll
        for (int ax = 0; ax < 3; ++ax) {
            const float cv = ((ax == 0) ? c0 : (ax == 1) ? c1 : c2) * 255.0f;
            const float minf = fmaxf(cv - cut, 0.0f);
            const float maxf = fminf(cv + cut, 255.0f);
            const int   mini = (int)floorf(minf);
            const int   maxi = min((int)floorf(maxf) + 1, VOLD);
            s_bnd[warp][lane][ax] = (maxi << 16) | mini;
        }
    }
    if (lane == 0) g_cnt[tile] = 0;       // restore invariant for next launch
    __syncwarp();

    const int tzi = tile & (NTZ - 1);
    const int tyi = (tile >> 4) & (NTY - 1);
    const int txi = tile >> 9;

    // Phase 2: weight loop. Lanes 0-7 wx, 8-15 wy, 16-31 wz.
    {
        const int axis = min(lane >> 3, 2);
        const int o    = lane - (axis << 3);
        const int tb   = (axis == 0) ? txi * TSX
                       : ((axis == 1) ? tyi * TSY : tzi * TSZ);
        const int idxv = tb + o;
        const float pos = (float)idxv * (1.0f / 255.0f);

#pragma unroll 4
        for (int p = 0; p < cnt; ++p) {
            const float c    = s_par[warp][p][axis];
            const float a    = s_par[warp][p][3];
            const int   bnd  = s_bnd[warp][p][axis];
            const int   mini = bnd & 0xFFFF;
            const int   maxi = bnd >> 16;

            float w = 0.0f;
            if (idxv >= mini && idxv < maxi) {
                const float d = pos - c;
                w = __expf(-d * d * a);
            }
            if (axis == 0) w *= s_par[warp][p][4];
            s_w[warp][p * SLICE + lane] = w;
        }
    }
    __syncwarp();

    // Phase 3: FMA. Lane owns (y, zq); accumulate all 8 x slabs.
    const int y  = lane >> 2;             // 0..7
    const int zq = lane & 3;              // 0..3
    const float* __restrict__ swp = s_w[warp];

    float acc[8][4];
#pragma unroll
    for (int i = 0; i < 8; ++i)
#pragma unroll
        for (int j = 0; j < 4; ++j) acc[i][j] = 0.f;

#pragma unroll 2
    for (int p = 0; p < cnt; ++p) {
        const float* s = swp + p * SLICE;
        const float  wy = s[8 + y];                       // 8 distinct
        const float4 wz = *(const float4*)(s + 16 + 4 * zq);  // 64B/warp
        float4 tz;
        tz.x = wy * wz.x; tz.y = wy * wz.y;
        tz.z = wy * wz.z; tz.w = wy * wz.w;
        const float4 wxa = *(const float4*)(s);           // warp-uniform
        const float4 wxb = *(const float4*)(s + 4);       // warp-uniform
        const float wx[8] = { wxa.x, wxa.y, wxa.z, wxa.w,
                              wxb.x, wxb.y, wxb.z, wxb.w };
#pragma unroll
        for (int xx = 0; xx < 8; ++xx) {
            acc[xx][0] = fmaf(wx[xx], tz.x, acc[xx][0]);
            acc[xx][1] = fmaf(wx[xx], tz.y, acc[xx][1]);
            acc[xx][2] = fmaf(wx[xx], tz.z, acc[xx][2]);
            acc[xx][3] = fmaf(wx[xx], tz.w, acc[xx][3]);
        }
    }

    // Stores: per x one STG.128; 4-lane groups write contiguous 64B z-rows.
    float* base = vol + ((size_t)(txi * TSX) * VOLD + (tyi * TSY + y)) * VOLD
                      + tzi * TSZ + 4 * zq;
#pragma unroll
    for (int xx = 0; xx < 8; ++xx) {
        *(float4*)(base + (size_t)xx * VOLD * VOLD) =
            make_float4(acc[xx][0], acc[xx][1], acc[xx][2], acc[xx][3]);
    }
}

// ---------------------------------------------------------------------------
extern "C" void kernel_launch(void* const* d_in, const int* in_sizes, int n_in,
                              void* d_out, int out_size) {
    const float* centers = (const float*)d_in[0];
    const float* sigmas  = (const float*)d_in[1];
    const float* intens  = (const float*)d_in[2];
    float* vol = (float*)d_out;

    prep_kernel<<<NGAUSS / 8, 256>>>(centers, sigmas);
    gather_kernel<<<NTILES / 4, 128>>>(centers, sigmas, intens, vol);
}